// round 1
// baseline (speedup 1.0000x reference)
#include <cuda_runtime.h>

#define BB 8
#define CC 64
#define HH 128
#define WW 128
#define HWP (HH*WW)
#define K2 9
#define OFFC 18
#define MASKC 9
#define NOUT 27      // 18 offset + 9 mask channels
#define NOUTP 28     // padded to multiple of 4 for float4 smem reads

// Scratch for intermediate offset/mask feature maps (graph-safe static device mem)
__device__ float g_offset[BB * OFFC * HWP];   // ~9.4 MB
__device__ float g_mask  [BB * MASKC * HWP];  // ~4.7 MB

// ---------------------------------------------------------------------------
// Kernel 1: fused 3x3 conv producing 18 offset channels + 9 sigmoid(mask)
// channels. One thread per output pixel (block = one row of one batch image).
// Weights staged in smem in [cchunk][tap][co] layout, co contiguous & padded
// so the inner product uses LDS.128 broadcasts.
// ---------------------------------------------------------------------------
__global__ __launch_bounds__(128) void offmask_kernel(
    const float* __restrict__ x,
    const float* __restrict__ w_off,
    const float* __restrict__ w_msk)
{
    const int w = threadIdx.x;
    const int h = blockIdx.x;
    const int b = blockIdx.y;

    __shared__ float ws[16 * 9 * NOUTP];   // 16 channels x 9 taps x 28 outputs

    float acc[NOUTP];
#pragma unroll
    for (int i = 0; i < NOUTP; i++) acc[i] = 0.f;

    for (int c0 = 0; c0 < CC; c0 += 16) {
        __syncthreads();
        for (int i = threadIdx.x; i < 16 * 9 * NOUTP; i += 128) {
            int co  = i % NOUTP;
            int r   = i / NOUTP;
            int tap = r % 9;
            int cc  = r / 9;
            int c   = c0 + cc;
            float v = 0.f;
            if (co < OFFC)      v = w_off[(co * CC + c) * 9 + tap];
            else if (co < NOUT) v = w_msk[((co - OFFC) * CC + c) * 9 + tap];
            ws[i] = v;
        }
        __syncthreads();

#pragma unroll 1
        for (int cc = 0; cc < 16; cc++) {
            const float* xc = x + (size_t)((b * CC + c0 + cc)) * HWP;
            float xv[9];
#pragma unroll
            for (int dy = 0; dy < 3; dy++) {
                int yy = h + dy - 1;
                bool yok = (yy >= 0) && (yy < HH);
#pragma unroll
                for (int dx = 0; dx < 3; dx++) {
                    int xx = w + dx - 1;
                    bool ok = yok && (xx >= 0) && (xx < WW);
                    xv[dy * 3 + dx] = ok ? __ldg(xc + yy * WW + xx) : 0.f;
                }
            }
#pragma unroll
            for (int tap = 0; tap < 9; tap++) {
                float v = xv[tap];
                const float4* wr = (const float4*)(ws + (cc * 9 + tap) * NOUTP);
#pragma unroll
                for (int q = 0; q < 7; q++) {
                    float4 wv = wr[q];
                    acc[4 * q + 0] += wv.x * v;
                    acc[4 * q + 1] += wv.y * v;
                    acc[4 * q + 2] += wv.z * v;
                    acc[4 * q + 3] += wv.w * v;
                }
            }
        }
    }

    const int pix = h * WW + w;
#pragma unroll
    for (int co = 0; co < OFFC; co++)
        g_offset[(b * OFFC + co) * HWP + pix] = acc[co];
#pragma unroll
    for (int cm = 0; cm < MASKC; cm++) {
        float v = acc[OFFC + cm];
        g_mask[(b * MASKC + cm) * HWP + pix] = 1.f / (1.f + __expf(-v));
    }
}

// ---------------------------------------------------------------------------
// Kernel 2: deformable sampling + einsum. One thread per output pixel, 64
// output-channel accumulators in registers. For each of the 9 kernel taps:
// compute bilinear corner weights once (channel-independent), fold in mask,
// then rank-1-update all 64 outputs per input channel with the per-k weight
// slice staged in smem ([c][co], co contiguous -> LDS.128 broadcast).
// ---------------------------------------------------------------------------
__global__ __launch_bounds__(128) void deform_kernel(
    const float* __restrict__ x,
    const float* __restrict__ w_conv,
    float* __restrict__ out)
{
    const int w = threadIdx.x;
    const int h = blockIdx.x;
    const int b = blockIdx.y;

    __shared__ float ws[CC * 64];   // [c][co], 16 KB

    float acc[64];
#pragma unroll
    for (int i = 0; i < 64; i++) acc[i] = 0.f;

    const int pix = h * WW + w;
    const float* xb = x + (size_t)b * CC * HWP;

    for (int k = 0; k < K2; k++) {
        __syncthreads();
        for (int i = threadIdx.x; i < CC * 64; i += 128) {
            int co = i & 63;
            int c  = i >> 6;
            ws[i] = w_conv[(co * CC + c) * 9 + k];
        }
        __syncthreads();

        const int ki = k / 3, kj = k % 3;
        float offy = g_offset[(b * OFFC + 2 * k    ) * HWP + pix];
        float offx = g_offset[(b * OFFC + 2 * k + 1) * HWP + pix];
        float m    = g_mask  [(b * MASKC + k       ) * HWP + pix];

        float py = (float)(h + ki - 1) + offy;
        float px = (float)(w + kj - 1) + offx;
        float y0f = floorf(py), x0f = floorf(px);
        int   y0 = (int)y0f,    x0 = (int)x0f;
        int   y1 = y0 + 1,      x1 = x0 + 1;
        float wy1 = py - y0f,   wx1 = px - x0f;
        float wy0 = 1.f - wy1,  wx0 = 1.f - wx1;

        bool v_y0 = (y0 >= 0) && (y0 < HH), v_y1 = (y1 >= 0) && (y1 < HH);
        bool v_x0 = (x0 >= 0) && (x0 < WW), v_x1 = (x1 >= 0) && (x1 < WW);

        float w00 = (v_y0 && v_x0) ? wy0 * wx0 : 0.f;
        float w01 = (v_y0 && v_x1) ? wy0 * wx1 : 0.f;
        float w10 = (v_y1 && v_x0) ? wy1 * wx0 : 0.f;
        float w11 = (v_y1 && v_x1) ? wy1 * wx1 : 0.f;
        w00 *= m; w01 *= m; w10 *= m; w11 *= m;

        int yc0 = min(max(y0, 0), HH - 1), yc1 = min(max(y1, 0), HH - 1);
        int xc0 = min(max(x0, 0), WW - 1), xc1 = min(max(x1, 0), WW - 1);
        int i00 = yc0 * WW + xc0, i01 = yc0 * WW + xc1;
        int i10 = yc1 * WW + xc0, i11 = yc1 * WW + xc1;

#pragma unroll 2
        for (int c = 0; c < CC; c++) {
            const float* xp = xb + c * HWP;
            float s = w00 * __ldg(xp + i00) + w01 * __ldg(xp + i01)
                    + w10 * __ldg(xp + i10) + w11 * __ldg(xp + i11);
            const float4* wr = (const float4*)(ws + c * 64);
#pragma unroll
            for (int q = 0; q < 16; q++) {
                float4 wv = wr[q];
                acc[4 * q + 0] += wv.x * s;
                acc[4 * q + 1] += wv.y * s;
                acc[4 * q + 2] += wv.z * s;
                acc[4 * q + 3] += wv.w * s;
            }
        }
    }

    float* op = out + (size_t)b * 64 * HWP + pix;
#pragma unroll
    for (int co = 0; co < 64; co++)
        op[co * HWP] = acc[co];
}

// ---------------------------------------------------------------------------
extern "C" void kernel_launch(void* const* d_in, const int* in_sizes, int n_in,
                              void* d_out, int out_size)
{
    const float* x      = (const float*)d_in[0];
    const float* w_conv = (const float*)d_in[1];
    const float* w_off  = (const float*)d_in[2];
    const float* w_msk  = (const float*)d_in[3];

    dim3 grid(HH, BB);
    offmask_kernel<<<grid, 128>>>(x, w_off, w_msk);
    deform_kernel<<<grid, 128>>>(x, w_conv, (float*)d_out);
}

// round 2
// speedup vs baseline: 1.2774x; 1.2774x over previous
#include <cuda_runtime.h>

#define BB 8
#define CC 64
#define HH 128
#define WW 128
#define HWP (HH*WW)
#define K2 9
#define OFFC 18
#define MASKC 9
#define NOUT 27
#define NOUTP 28

// Graph-safe static device scratch
__device__ float g_offset[BB * OFFC * HWP];   // offset maps
__device__ float g_mask  [BB * MASKC * HWP];  // sigmoid(mask) maps
__device__ float g_wt    [K2 * CC * CC];      // w_conv transposed to [k][c][co]

// ---------------------------------------------------------------------------
// Tiny transpose: w_conv [co][c][k] -> g_wt [k][c][co]
// ---------------------------------------------------------------------------
__global__ void wtrans_kernel(const float* __restrict__ w_conv)
{
    int i = blockIdx.x * 256 + threadIdx.x;
    if (i < K2 * CC * CC) {
        int co = i & 63;
        int c  = (i >> 6) & 63;
        int k  = i >> 12;
        g_wt[i] = w_conv[(co * CC + c) * K2 + k];
    }
}

// ---------------------------------------------------------------------------
// Kernel 1: fused 3x3 conv producing 18 offset channels + 9 sigmoid(mask).
// (unchanged from round 1)
// ---------------------------------------------------------------------------
__global__ __launch_bounds__(128) void offmask_kernel(
    const float* __restrict__ x,
    const float* __restrict__ w_off,
    const float* __restrict__ w_msk)
{
    const int w = threadIdx.x;
    const int h = blockIdx.x;
    const int b = blockIdx.y;

    __shared__ float ws[16 * 9 * NOUTP];

    float acc[NOUTP];
#pragma unroll
    for (int i = 0; i < NOUTP; i++) acc[i] = 0.f;

    for (int c0 = 0; c0 < CC; c0 += 16) {
        __syncthreads();
        for (int i = threadIdx.x; i < 16 * 9 * NOUTP; i += 128) {
            int co  = i % NOUTP;
            int r   = i / NOUTP;
            int tap = r % 9;
            int cc  = r / 9;
            int c   = c0 + cc;
            float v = 0.f;
            if (co < OFFC)      v = w_off[(co * CC + c) * 9 + tap];
            else if (co < NOUT) v = w_msk[((co - OFFC) * CC + c) * 9 + tap];
            ws[i] = v;
        }
        __syncthreads();

#pragma unroll 1
        for (int cc = 0; cc < 16; cc++) {
            const float* xc = x + (size_t)((b * CC + c0 + cc)) * HWP;
            float xv[9];
#pragma unroll
            for (int dy = 0; dy < 3; dy++) {
                int yy = h + dy - 1;
                bool yok = (yy >= 0) && (yy < HH);
#pragma unroll
                for (int dx = 0; dx < 3; dx++) {
                    int xx = w + dx - 1;
                    bool ok = yok && (xx >= 0) && (xx < WW);
                    xv[dy * 3 + dx] = ok ? __ldg(xc + yy * WW + xx) : 0.f;
                }
            }
#pragma unroll
            for (int tap = 0; tap < 9; tap++) {
                float v = xv[tap];
                const float4* wr = (const float4*)(ws + (cc * 9 + tap) * NOUTP);
#pragma unroll
                for (int q = 0; q < 7; q++) {
                    float4 wv = wr[q];
                    acc[4 * q + 0] += wv.x * v;
                    acc[4 * q + 1] += wv.y * v;
                    acc[4 * q + 2] += wv.z * v;
                    acc[4 * q + 3] += wv.w * v;
                }
            }
        }
    }

    const int pix = h * WW + w;
#pragma unroll
    for (int co = 0; co < OFFC; co++)
        g_offset[(b * OFFC + co) * HWP + pix] = acc[co];
#pragma unroll
    for (int cm = 0; cm < MASKC; cm++) {
        float v = acc[OFFC + cm];
        g_mask[(b * MASKC + cm) * HWP + pix] = 1.f / (1.f + __expf(-v));
    }
}

// ---------------------------------------------------------------------------
// Kernel 2 (restructured): per kernel tap k:
//   phase A: 128 threads compute per-pixel bilinear corner indices/weights
//            (mask folded in); all threads stage W[c][co] slice for this k.
//   phase B: 256 threads sample S[c][pix] = sum_corners wt*x  -> smem.
//   phase C: register-tiled GEMM: each thread owns 8co x 4pix accumulators;
//            per channel: 2 broadcast LDS.128 (weights) + 1 LDS.128 (S)
//            feed 32 FMAs.  (was: 1 LDS.128 per 4 FMAs)
// ---------------------------------------------------------------------------
#define SM_S    0                         // float [64][128]   32 KB
#define SM_W    (CC * 128)                // float [64][64]    16 KB
#define SM_IDX  (SM_W + CC * CC)          // int   [128][4]     2 KB
#define SM_WT   (SM_IDX + 128 * 4)        // float [128][4]     2 KB
#define SM_TOT  (SM_WT + 128 * 4)         // floats total (13312 = 52 KB)

__global__ __launch_bounds__(256) void deform_kernel(
    const float* __restrict__ x,
    float* __restrict__ out)
{
    extern __shared__ float sm[];
    float* sS   = sm + SM_S;
    float* sW   = sm + SM_W;
    int*   sIdx = (int*)(sm + SM_IDX);
    float* sWt  = sm + SM_WT;

    const int t = threadIdx.x;
    const int h = blockIdx.x;
    const int b = blockIdx.y;

    float acc[32];
#pragma unroll
    for (int i = 0; i < 32; i++) acc[i] = 0.f;

    const float* xb = x + (size_t)b * CC * HWP;

    const int co0   = (t >> 5) << 3;   // 0,8,...,56
    const int pix0  = (t & 31) << 2;   // 0,4,...,124
    const int cbase = (t >> 7) * 32;   // 0 or 32
    const int spix  = t & 127;

#pragma unroll 1
    for (int k = 0; k < K2; k++) {
        __syncthreads();   // prior GEMM done reading sS/sW

        // stage W[c][co] for this k (coalesced from pre-transposed g_wt)
        const float* wk = g_wt + k * CC * CC;
#pragma unroll
        for (int i = 0; i < 16; i++)
            sW[t + 256 * i] = wk[t + 256 * i];

        // per-pixel bilinear params
        if (t < 128) {
            const int w   = t;
            const int pix = h * WW + w;
            float offy = g_offset[(b * OFFC + 2 * k    ) * HWP + pix];
            float offx = g_offset[(b * OFFC + 2 * k + 1) * HWP + pix];
            float m    = g_mask  [(b * MASKC + k       ) * HWP + pix];

            const int ki = k / 3, kj = k % 3;
            float py = (float)(h + ki - 1) + offy;
            float px = (float)(w + kj - 1) + offx;
            float y0f = floorf(py), x0f = floorf(px);
            int   y0 = (int)y0f,    x0 = (int)x0f;
            int   y1 = y0 + 1,      x1 = x0 + 1;
            float wy1 = py - y0f,   wx1 = px - x0f;
            float wy0 = 1.f - wy1,  wx0 = 1.f - wx1;

            bool vy0 = (y0 >= 0) && (y0 < HH), vy1 = (y1 >= 0) && (y1 < HH);
            bool vx0 = (x0 >= 0) && (x0 < WW), vx1 = (x1 >= 0) && (x1 < WW);

            float w00 = (vy0 && vx0) ? wy0 * wx0 * m : 0.f;
            float w01 = (vy0 && vx1) ? wy0 * wx1 * m : 0.f;
            float w10 = (vy1 && vx0) ? wy1 * wx0 * m : 0.f;
            float w11 = (vy1 && vx1) ? wy1 * wx1 * m : 0.f;

            int yc0 = min(max(y0, 0), HH - 1), yc1 = min(max(y1, 0), HH - 1);
            int xc0 = min(max(x0, 0), WW - 1), xc1 = min(max(x1, 0), WW - 1);

            sIdx[4 * w + 0] = yc0 * WW + xc0;
            sIdx[4 * w + 1] = yc0 * WW + xc1;
            sIdx[4 * w + 2] = yc1 * WW + xc0;
            sIdx[4 * w + 3] = yc1 * WW + xc1;
            sWt[4 * w + 0] = w00;
            sWt[4 * w + 1] = w01;
            sWt[4 * w + 2] = w10;
            sWt[4 * w + 3] = w11;
        }
        __syncthreads();   // params + W ready

        // sampling: this thread covers channels [cbase, cbase+32) at pixel spix
        {
            int4   idx = *(const int4*)  (sIdx + 4 * spix);
            float4 wt  = *(const float4*)(sWt  + 4 * spix);
            const float* p = xb + (size_t)cbase * HWP;
#pragma unroll 4
            for (int j = 0; j < 32; j++) {
                float s = wt.x * __ldg(p + idx.x);
                s = fmaf(wt.y, __ldg(p + idx.y), s);
                s = fmaf(wt.z, __ldg(p + idx.z), s);
                s = fmaf(wt.w, __ldg(p + idx.w), s);
                sS[(cbase + j) * 128 + spix] = s;
                p += HWP;
            }
        }
        __syncthreads();   // S ready

        // register-tiled GEMM: acc[co_i][pix_j] += W[c][co0+i] * S[c][pix0+j]
#pragma unroll 8
        for (int c = 0; c < CC; c++) {
            float4 s  = *(const float4*)(sS + c * 128 + pix0);
            float4 wa = *(const float4*)(sW + c * CC + co0);
            float4 wb = *(const float4*)(sW + c * CC + co0 + 4);
            acc[ 0] = fmaf(wa.x, s.x, acc[ 0]);
            acc[ 1] = fmaf(wa.x, s.y, acc[ 1]);
            acc[ 2] = fmaf(wa.x, s.z, acc[ 2]);
            acc[ 3] = fmaf(wa.x, s.w, acc[ 3]);
            acc[ 4] = fmaf(wa.y, s.x, acc[ 4]);
            acc[ 5] = fmaf(wa.y, s.y, acc[ 5]);
            acc[ 6] = fmaf(wa.y, s.z, acc[ 6]);
            acc[ 7] = fmaf(wa.y, s.w, acc[ 7]);
            acc[ 8] = fmaf(wa.z, s.x, acc[ 8]);
            acc[ 9] = fmaf(wa.z, s.y, acc[ 9]);
            acc[10] = fmaf(wa.z, s.z, acc[10]);
            acc[11] = fmaf(wa.z, s.w, acc[11]);
            acc[12] = fmaf(wa.w, s.x, acc[12]);
            acc[13] = fmaf(wa.w, s.y, acc[13]);
            acc[14] = fmaf(wa.w, s.z, acc[14]);
            acc[15] = fmaf(wa.w, s.w, acc[15]);
            acc[16] = fmaf(wb.x, s.x, acc[16]);
            acc[17] = fmaf(wb.x, s.y, acc[17]);
            acc[18] = fmaf(wb.x, s.z, acc[18]);
            acc[19] = fmaf(wb.x, s.w, acc[19]);
            acc[20] = fmaf(wb.y, s.x, acc[20]);
            acc[21] = fmaf(wb.y, s.y, acc[21]);
            acc[22] = fmaf(wb.y, s.z, acc[22]);
            acc[23] = fmaf(wb.y, s.w, acc[23]);
            acc[24] = fmaf(wb.z, s.x, acc[24]);
            acc[25] = fmaf(wb.z, s.y, acc[25]);
            acc[26] = fmaf(wb.z, s.z, acc[26]);
            acc[27] = fmaf(wb.z, s.w, acc[27]);
            acc[28] = fmaf(wb.w, s.x, acc[28]);
            acc[29] = fmaf(wb.w, s.y, acc[29]);
            acc[30] = fmaf(wb.w, s.z, acc[30]);
            acc[31] = fmaf(wb.w, s.w, acc[31]);
        }
    }

    // epilogue
    float* ob = out + (size_t)b * CC * HWP + h * WW;
#pragma unroll
    for (int i = 0; i < 8; i++)
#pragma unroll
        for (int j = 0; j < 4; j++)
            ob[(size_t)(co0 + i) * HWP + pix0 + j] = acc[i * 4 + j];
}

// ---------------------------------------------------------------------------
extern "C" void kernel_launch(void* const* d_in, const int* in_sizes, int n_in,
                              void* d_out, int out_size)
{
    const float* x      = (const float*)d_in[0];
    const float* w_conv = (const float*)d_in[1];
    const float* w_off  = (const float*)d_in[2];
    const float* w_msk  = (const float*)d_in[3];

    static bool attr_set = false;
    if (!attr_set) {
        cudaFuncSetAttribute(deform_kernel,
                             cudaFuncAttributeMaxDynamicSharedMemorySize,
                             SM_TOT * sizeof(float));
        attr_set = true;
    }

    wtrans_kernel<<<(K2 * CC * CC + 255) / 256, 256>>>(w_conv);
    offmask_kernel<<<dim3(HH, BB), 128>>>(x, w_off, w_msk);
    deform_kernel<<<dim3(HH, BB), 256, SM_TOT * sizeof(float)>>>(x, (float*)d_out);
}

// round 4
// speedup vs baseline: 1.6803x; 1.3154x over previous
#include <cuda_runtime.h>
#include <cuda_bf16.h>
#include <cstdint>

#define BB 8
#define CC 64
#define HH 128
#define WW 128
#define HWP (HH*WW)
#define K2 9
#define OFFC 18
#define MASKC 9
#define NOUT 27
#define NOUTP 28

// ---------------------------------------------------------------------------
// Device scratch (graph-safe)
// ---------------------------------------------------------------------------
__device__ float g_offset[BB * OFFC * HWP];
__device__ float g_mask  [BB * MASKC * HWP];
// W in mma-fragment order: [tap][hi/lo][nn(8)][kk(4)][lane(32)] x uint2
__device__ __align__(16) uint2 g_wfrag[K2 * 2 * 8 * 4 * 32];

__device__ __forceinline__ uint32_t smem_u32(const void* p) {
    uint32_t a;
    asm("{ .reg .u64 t; cvta.to.shared.u64 t, %1; cvt.u32.u64 %0, t; }" : "=r"(a) : "l"(p));
    return a;
}

__device__ __forceinline__ void ldm_x4(uint32_t* r, uint32_t addr) {
    asm volatile("ldmatrix.sync.aligned.m8n8.x4.shared.b16 {%0,%1,%2,%3}, [%4];"
        : "=r"(r[0]), "=r"(r[1]), "=r"(r[2]), "=r"(r[3]) : "r"(addr));
}

__device__ __forceinline__ void mma16816(float* d, const uint32_t* a, const uint32_t* b) {
    asm volatile(
        "mma.sync.aligned.m16n8k16.row.col.f32.bf16.bf16.f32 "
        "{%0,%1,%2,%3}, {%4,%5,%6,%7}, {%8,%9}, {%0,%1,%2,%3};"
        : "+f"(d[0]), "+f"(d[1]), "+f"(d[2]), "+f"(d[3])
        : "r"(a[0]), "r"(a[1]), "r"(a[2]), "r"(a[3]), "r"(b[0]), "r"(b[1]));
}

// ---------------------------------------------------------------------------
// Setup: w_conv [co][c][k] -> fragment-ordered bf16 hi/lo tiles
// b0 = W[co][cbase + {0,1}], b1 = W[co][cbase + 8 + {0,1}]  (packed lo|hi)
// ---------------------------------------------------------------------------
__global__ void wfrag_kernel(const float* __restrict__ w_conv)
{
    int i = blockIdx.x * 256 + threadIdx.x;
    if (i >= K2 * 2 * 8 * 4 * 32) return;
    int lane = i & 31;
    int kk   = (i >> 5) & 3;
    int nn   = (i >> 7) & 7;
    int hl   = (i >> 10) & 1;
    int k    = i >> 11;

    int co    = nn * 8 + (lane >> 2);
    int cbase = kk * 16 + 2 * (lane & 3);

    uint32_t regs[2];
#pragma unroll
    for (int r = 0; r < 2; r++) {
        uint32_t pk = 0;
#pragma unroll
        for (int j = 0; j < 2; j++) {
            int c = cbase + r * 8 + j;
            float wv = w_conv[(co * CC + c) * K2 + k];
            __nv_bfloat16 hi = __float2bfloat16(wv);
            float lov = wv - __bfloat162float(hi);
            __nv_bfloat16 v = hl ? __float2bfloat16(lov) : hi;
            pk |= ((uint32_t)__bfloat16_as_ushort(v)) << (16 * j);
        }
        regs[r] = pk;
    }
    g_wfrag[i] = make_uint2(regs[0], regs[1]);
}

// ---------------------------------------------------------------------------
// Kernel 1: offset/mask 3x3 conv (unchanged from round 2)
// ---------------------------------------------------------------------------
__global__ __launch_bounds__(128) void offmask_kernel(
    const float* __restrict__ x,
    const float* __restrict__ w_off,
    const float* __restrict__ w_msk)
{
    const int w = threadIdx.x;
    const int h = blockIdx.x;
    const int b = blockIdx.y;

    __shared__ float ws[16 * 9 * NOUTP];

    float acc[NOUTP];
#pragma unroll
    for (int i = 0; i < NOUTP; i++) acc[i] = 0.f;

    for (int c0 = 0; c0 < CC; c0 += 16) {
        __syncthreads();
        for (int i = threadIdx.x; i < 16 * 9 * NOUTP; i += 128) {
            int co  = i % NOUTP;
            int r   = i / NOUTP;
            int tap = r % 9;
            int cc  = r / 9;
            int c   = c0 + cc;
            float v = 0.f;
            if (co < OFFC)      v = w_off[(co * CC + c) * 9 + tap];
            else if (co < NOUT) v = w_msk[((co - OFFC) * CC + c) * 9 + tap];
            ws[i] = v;
        }
        __syncthreads();

#pragma unroll 1
        for (int cc = 0; cc < 16; cc++) {
            const float* xc = x + (size_t)((b * CC + c0 + cc)) * HWP;
            float xv[9];
#pragma unroll
            for (int dy = 0; dy < 3; dy++) {
                int yy = h + dy - 1;
                bool yok = (yy >= 0) && (yy < HH);
#pragma unroll
                for (int dx = 0; dx < 3; dx++) {
                    int xx = w + dx - 1;
                    bool ok = yok && (xx >= 0) && (xx < WW);
                    xv[dy * 3 + dx] = ok ? __ldg(xc + yy * WW + xx) : 0.f;
                }
            }
#pragma unroll
            for (int tap = 0; tap < 9; tap++) {
                float v = xv[tap];
                const float4* wr = (const float4*)(ws + (cc * 9 + tap) * NOUTP);
#pragma unroll
                for (int q = 0; q < 7; q++) {
                    float4 wv = wr[q];
                    acc[4 * q + 0] += wv.x * v;
                    acc[4 * q + 1] += wv.y * v;
                    acc[4 * q + 2] += wv.z * v;
                    acc[4 * q + 3] += wv.w * v;
                }
            }
        }
    }

    const int pix = h * WW + w;
#pragma unroll
    for (int co = 0; co < OFFC; co++)
        g_offset[(b * OFFC + co) * HWP + pix] = acc[co];
#pragma unroll
    for (int cm = 0; cm < MASKC; cm++) {
        float v = acc[OFFC + cm];
        g_mask[(b * MASKC + cm) * HWP + pix] = 1.f / (1.f + __expf(-v));
    }
}

// ---------------------------------------------------------------------------
// Kernel 2: deform via mma.sync (bf16 hi/lo split, fp32 accum).
// Block = one (b,h) row, 128 threads = 4 warps; warp w owns pixels [32w,32w+32).
// D[128 pix x 64 co] lives in registers across all 9 taps.
// ---------------------------------------------------------------------------
#define SMEM_BYTES (16384 * 3 + 1024)

__global__ __launch_bounds__(128) void deform_kernel(
    const float* __restrict__ x, float* __restrict__ out)
{
    extern __shared__ char smraw[];
    const uint32_t raw_u  = smem_u32(smraw);
    const uint32_t base_u = (raw_u + 1023) & ~1023u;
    char* const smb = smraw + (base_u - raw_u);

    const uint32_t uAhi = base_u;            // 16 KB: [128 pix][64 c] bf16, SW128
    const uint32_t uAlo = base_u + 16384;    // 16 KB
    char* const sWf = smb + 32768;           // 16 KB: fragment-ordered W (hi+lo)

    const int t    = threadIdx.x;
    const int lane = t & 31;
    const int wrp  = t >> 5;
    const int h    = blockIdx.x;
    const int b    = blockIdx.y;

    float acc[64];   // [mt(2)][nn(8)][q(4)]
#pragma unroll
    for (int i = 0; i < 64; i++) acc[i] = 0.f;

    const float* xb = x + (size_t)b * CC * HWP;

    // precomputed ldmatrix lane addresses (per mt, kk): row r, chunk swizzled
    uint32_t lda[2][4];
#pragma unroll
    for (int mt = 0; mt < 2; mt++) {
        int r = wrp * 32 + mt * 16 + (lane & 15);
#pragma unroll
        for (int kk = 0; kk < 4; kk++) {
            int chunk = kk * 2 + (lane >> 4);
            lda[mt][kk] = (uint32_t)(r * 128 + ((chunk ^ (r & 7)) * 16));
        }
    }

#pragma unroll 1
    for (int k = 0; k < K2; k++) {
        __syncthreads();   // previous tap's mma reads done

        // ---- stage W fragments for this tap (16 KB) ----
        {
            const uint4* src = (const uint4*)(g_wfrag + (size_t)k * 2048);
            uint4* dst = (uint4*)sWf;
#pragma unroll
            for (int i = 0; i < 8; i++)
                dst[t + 128 * i] = src[t + 128 * i];
        }

        // ---- bilinear params for this thread's pixel ----
        const int w   = t;
        const int pix = h * WW + w;
        float offy = g_offset[(b * OFFC + 2 * k    ) * HWP + pix];
        float offx = g_offset[(b * OFFC + 2 * k + 1) * HWP + pix];
        float m    = g_mask  [(b * MASKC + k       ) * HWP + pix];

        const int ki = k / 3, kj = k % 3;
        float py = (float)(h + ki - 1) + offy;
        float px = (float)(w + kj - 1) + offx;
        float y0f = floorf(py), x0f = floorf(px);
        int   y0 = (int)y0f,    x0 = (int)x0f;
        int   y1 = y0 + 1,      x1 = x0 + 1;
        float wy1 = py - y0f,   wx1 = px - x0f;
        float wy0 = 1.f - wy1,  wx0 = 1.f - wx1;

        bool vy0 = (y0 >= 0) && (y0 < HH), vy1 = (y1 >= 0) && (y1 < HH);
        bool vx0 = (x0 >= 0) && (x0 < WW), vx1 = (x1 >= 0) && (x1 < WW);

        float w00 = (vy0 && vx0) ? wy0 * wx0 * m : 0.f;
        float w01 = (vy0 && vx1) ? wy0 * wx1 * m : 0.f;
        float w10 = (vy1 && vx0) ? wy1 * wx0 * m : 0.f;
        float w11 = (vy1 && vx1) ? wy1 * wx1 * m : 0.f;

        int yc0 = min(max(y0, 0), HH - 1), yc1 = min(max(y1, 0), HH - 1);
        int xc0 = min(max(x0, 0), WW - 1), xc1 = min(max(x1, 0), WW - 1);
        int i00 = yc0 * WW + xc0, i01 = yc0 * WW + xc1;
        int i10 = yc1 * WW + xc0, i11 = yc1 * WW + xc1;

        // ---- sample 64 channels, split hi/lo, st.128 into swizzled A tiles ----
#pragma unroll 1
        for (int cc = 0; cc < 8; cc++) {
            uint32_t Hq[4], Lq[4];
#pragma unroll
            for (int q = 0; q < 4; q++) {
                uint32_t hp = 0, lp = 0;
#pragma unroll
                for (int j = 0; j < 2; j++) {
                    const float* p = xb + (size_t)(cc * 8 + q * 2 + j) * HWP;
                    float v = w00 * __ldg(p + i00);
                    v = fmaf(w01, __ldg(p + i01), v);
                    v = fmaf(w10, __ldg(p + i10), v);
                    v = fmaf(w11, __ldg(p + i11), v);
                    __nv_bfloat16 hi = __float2bfloat16(v);
                    __nv_bfloat16 lo = __float2bfloat16(v - __bfloat162float(hi));
                    hp |= ((uint32_t)__bfloat16_as_ushort(hi)) << (16 * j);
                    lp |= ((uint32_t)__bfloat16_as_ushort(lo)) << (16 * j);
                }
                Hq[q] = hp; Lq[q] = lp;
            }
            uint32_t so = (uint32_t)(t * 128 + ((cc ^ (t & 7)) * 16));
            *(uint4*)(smb +          so) = make_uint4(Hq[0], Hq[1], Hq[2], Hq[3]);
            *(uint4*)(smb + 16384 + so) = make_uint4(Lq[0], Lq[1], Lq[2], Lq[3]);
        }

        __syncthreads();   // tiles + W ready

        // ---- 3 passes: Shi*Wh, Slo*Wh, Shi*Wl ----
#pragma unroll 1
        for (int pass = 0; pass < 3; pass++) {
            const uint32_t Abase = (pass == 1) ? uAlo : uAhi;
            const int hl = (pass == 2) ? 1 : 0;

            uint32_t afr[2][4][4];
#pragma unroll
            for (int mt = 0; mt < 2; mt++)
#pragma unroll
                for (int kk = 0; kk < 4; kk++)
                    ldm_x4(afr[mt][kk], Abase + lda[mt][kk]);

            const uint2* wf = (const uint2*)sWf + hl * 1024 + lane;
#pragma unroll
            for (int nn = 0; nn < 8; nn++) {
#pragma unroll
                for (int kk = 0; kk < 4; kk++) {
                    uint2 bb = wf[nn * 128 + kk * 32];
                    mma16816(acc + (0 * 8 + nn) * 4, afr[0][kk], &bb.x);
                    mma16816(acc + (1 * 8 + nn) * 4, afr[1][kk], &bb.x);
                }
            }
        }
    }

    // ---- epilogue: D[m][n] -> out[b][n][h*W + m] ----
    float* ob = out + (size_t)b * CC * HWP + h * WW;
#pragma unroll
    for (int mt = 0; mt < 2; mt++) {
        int m = wrp * 32 + mt * 16 + (lane >> 2);
#pragma unroll
        for (int nn = 0; nn < 8; nn++) {
            int n = nn * 8 + 2 * (lane & 3);
            const float* a = acc + (mt * 8 + nn) * 4;
            ob[(size_t)n * HWP + m]           = a[0];
            ob[(size_t)(n + 1) * HWP + m]     = a[1];
            ob[(size_t)n * HWP + m + 8]       = a[2];
            ob[(size_t)(n + 1) * HWP + m + 8] = a[3];
        }
    }
}

// ---------------------------------------------------------------------------
extern "C" void kernel_launch(void* const* d_in, const int* in_sizes, int n_in,
                              void* d_out, int out_size)
{
    const float* x      = (const float*)d_in[0];
    const float* w_conv = (const float*)d_in[1];
    const float* w_off  = (const float*)d_in[2];
    const float* w_msk  = (const float*)d_in[3];

    static bool attr_set = false;
    if (!attr_set) {
        cudaFuncSetAttribute(deform_kernel,
                             cudaFuncAttributeMaxDynamicSharedMemorySize,
                             SMEM_BYTES);
        attr_set = true;
    }

    wfrag_kernel<<<(K2 * 2 * 8 * 4 * 32 + 255) / 256, 256>>>(w_conv);
    offmask_kernel<<<dim3(HH, BB), 128>>>(x, w_off, w_msk);
    deform_kernel<<<dim3(HH, BB), 128, SMEM_BYTES>>>(x, (float*)d_out);
}